// round 6
// baseline (speedup 1.0000x reference)
#include <cuda_runtime.h>
#include <cuda_bf16.h>
#include <cstdint>

// TELIF: temporal-encoded LIF spiking neuron scan.
// tx: [T, B, N] f32, TE: [N, T] f32 -> ty: [T, B, N] f32.
//
// R6: DRAM row-locality attack. R1/R4/R5 (three different concurrency
// structures) all hit exactly 3.4-3.6 TB/s / 43% DRAM: the wall is the
// address pattern (every access 256KB-strided -> row miss per 128B line,
// scattered R/W turnaround), not request supply. Fix:
//  - 8 sequential launches of 64 t-steps each (state in __device__ scratch)
//    -> active window 16MB tx + 16MB out, L2-sized.
//  - launch k prefetches window k+1's tx into L2 as contiguous per-block
//    16KB pieces (sequential at DRAM); scan's strided reads then hit L2,
//    which persists across launches. Pre-kernel covers window 0.

#define T_STEPS 512
#define B_DIM   64
#define N_DIM   1024
#define BN      (B_DIM * N_DIM)

#define REST      0.0f
#define DECAY     0.2f
#define THRESHOLD 0.3f
#define BETA      0.02f

#define BLK      64                   // threads per block
#define NBLOCKS  (BN / BLK)           // 1024
#define T_BLOCK  64                   // steps per launch
#define NLAUNCH  (T_STEPS / T_BLOCK)  // 8
#define UNROLL   8

// Window size in floats / lines
#define WIN_F     (T_BLOCK * BN)            // 4M floats = 16MB
#define PIECE_F   (WIN_F / NBLOCKS)         // 4096 floats = 16KB per block
#define PF_LINES  (PIECE_F * 4 / 128)       // 128 lines per block
#define PF_PER_TH (PF_LINES / BLK)          // 2 lines per thread

__device__ float g_te_t[T_STEPS * N_DIM];   // TE transposed to [T][N]
__device__ float g_state[3 * BN];           // v | y | th

// ---------------------------------------------------------------------------
// Transpose TE [N, T] -> g_te_t [T, N]. 32x32 tiles, padded smem.
// ---------------------------------------------------------------------------
__global__ void telif_transpose_te(const float* __restrict__ TE) {
    __shared__ float tile[32][33];
    int n0 = blockIdx.x * 32;
    int t0 = blockIdx.y * 32;
    int lx = threadIdx.x;
    int ly = threadIdx.y;

#pragma unroll
    for (int i = 0; i < 32; i += 8)
        tile[ly + i][lx] = TE[(size_t)(n0 + ly + i) * T_STEPS + (t0 + lx)];
    __syncthreads();
#pragma unroll
    for (int i = 0; i < 32; i += 8)
        g_te_t[(size_t)(t0 + ly + i) * N_DIM + (n0 + lx)] = tile[lx][ly + i];
}

// ---------------------------------------------------------------------------
// L2 prefetch of one tx window as contiguous per-block pieces.
// ---------------------------------------------------------------------------
__device__ __forceinline__ void prefetch_window(const float* tx, int t0) {
    const float* base = tx + (size_t)t0 * BN + (size_t)blockIdx.x * PIECE_F;
#pragma unroll
    for (int j = 0; j < PF_PER_TH; j++) {
        const float* p = base + (size_t)(threadIdx.x * PF_PER_TH + j) * 32;
        asm volatile("prefetch.global.L2 [%0];" :: "l"(p));
    }
}

__global__ void __launch_bounds__(BLK)
telif_prefetch_w0(const float* __restrict__ tx) {
    prefetch_window(tx, 0);
}

// ---------------------------------------------------------------------------
// Scan one t-block [t0, t0 + T_BLOCK). One thread per (b, n).
// ---------------------------------------------------------------------------
__global__ void __launch_bounds__(BLK)
telif_scan_tb(const float* __restrict__ tx, float* __restrict__ out,
              int t0, int first, int last) {
    const int idx = blockIdx.x * BLK + threadIdx.x;   // b*N + n
    const int n   = idx & (N_DIM - 1);

    // Kick off next window's L2 prefetch before doing anything else.
    if (!last) prefetch_window(tx, t0 + T_BLOCK);

    const float* txp = tx + (size_t)t0 * BN + idx;
    float*       op  = out + (size_t)t0 * BN + idx;
    const float* tep = g_te_t + (size_t)t0 * N_DIM + n;

    float v, y, th;
    if (first) {
        v = REST; y = 0.0f; th = THRESHOLD;
    } else {
        v  = g_state[idx];
        y  = g_state[BN + idx];
        th = g_state[2 * BN + idx];
    }

#pragma unroll 1
    for (int tb = 0; tb < T_BLOCK; tb += UNROLL) {
        float xs[UNROLL], te[UNROLL];
#pragma unroll
        for (int u = 0; u < UNROLL; u++) {
            xs[u] = __ldcg(txp + (size_t)(tb + u) * BN);
            te[u] = __ldg(tep + (size_t)(tb + u) * N_DIM);
        }
#pragma unroll
        for (int u = 0; u < UNROLL; u++) {
            th = th + v * te[u] - (th - THRESHOLD) * BETA;
            v  = v * DECAY * (1.0f - y) + xs[u];
            y  = (v > th) ? 1.0f : 0.0f;
            op[(size_t)(tb + u) * BN] = y;
        }
    }

    if (!last) {
        g_state[idx]          = v;
        g_state[BN + idx]     = y;
        g_state[2 * BN + idx] = th;
    }
}

// ---------------------------------------------------------------------------
// Launch
// ---------------------------------------------------------------------------
extern "C" void kernel_launch(void* const* d_in, const int* in_sizes, int n_in,
                              void* d_out, int out_size) {
    const float* tx = (const float*)d_in[0];   // [T, B, N]
    const float* TE = (const float*)d_in[1];   // [N, T]
    float* out = (float*)d_out;                // [T, B, N]

    (void)in_sizes; (void)n_in; (void)out_size;

    telif_prefetch_w0<<<NBLOCKS, BLK>>>(tx);

    dim3 tb(32, 8);
    dim3 tg(N_DIM / 32, T_STEPS / 32);
    telif_transpose_te<<<tg, tb>>>(TE);

    for (int k = 0; k < NLAUNCH; k++) {
        telif_scan_tb<<<NBLOCKS, BLK>>>(tx, out, k * T_BLOCK,
                                        k == 0, k == NLAUNCH - 1);
    }
}